// round 11
// baseline (speedup 1.0000x reference)
#include <cuda_runtime.h>
#include <cuda.h>
#include <math.h>

#define B_DIM   4096
#define N_GENN  512
#define F_GEN   64
#define EMB     16
#define OUT_ROW 1025
#define THREADS 128
#define CH_ROWS 64            // rows per chunk; 16 rows per warp
#define CH_PER_B 8
#define STAGES  3
#define PF_DIST 6             // L2 prefetch distance (chunks)
#define WR_FLTS (16 * F_GEN)          // 1024 floats (4KB) per warp stage
#define GRID    608                   // 152 SMs x 4 CTAs persistent

// ---------------- shared device helpers ----------------

__device__ __forceinline__ void mma_tf32(float c[4], const unsigned a[4],
                                         unsigned b0, unsigned b1) {
    asm volatile(
        "mma.sync.aligned.m16n8k8.row.col.f32.tf32.tf32.f32 "
        "{%0,%1,%2,%3}, {%4,%5,%6,%7}, {%8,%9}, {%0,%1,%2,%3};"
        : "+f"(c[0]), "+f"(c[1]), "+f"(c[2]), "+f"(c[3])
        : "r"(a[0]), "r"(a[1]), "r"(a[2]), "r"(a[3]), "r"(b0), "r"(b1));
}

__device__ __forceinline__ void ldsm4(unsigned r[4], unsigned addr) {
    asm volatile("ldmatrix.sync.aligned.m8n8.x4.shared.b16 {%0,%1,%2,%3}, [%4];"
                 : "=r"(r[0]), "=r"(r[1]), "=r"(r[2]), "=r"(r[3]) : "r"(addr));
}

__device__ __forceinline__ unsigned s2u(const void* p) {
    return (unsigned)__cvta_generic_to_shared(p);
}

__device__ __forceinline__ void mbar_init(unsigned mb, unsigned cnt) {
    asm volatile("mbarrier.init.shared.b64 [%0], %1;" :: "r"(mb), "r"(cnt) : "memory");
}
__device__ __forceinline__ void mbar_expect_tx(unsigned mb, unsigned bytes) {
    asm volatile("mbarrier.arrive.expect_tx.shared.b64 _, [%0], %1;"
                 :: "r"(mb), "r"(bytes) : "memory");
}
__device__ __forceinline__ void mbar_wait(unsigned mb, unsigned parity) {
    asm volatile(
        "{\n\t"
        ".reg .pred P%=;\n\t"
        "W%=:\n\t"
        "mbarrier.try_wait.parity.acquire.cta.shared::cta.b64 P%=, [%0], %1, 0x989680;\n\t"
        "@P%= bra D%=;\n\t"
        "bra W%=;\n\t"
        "D%=:\n\t"
        "}"
        :: "r"(mb), "r"(parity) : "memory");
}
__device__ __forceinline__ void tma2d(unsigned dst, const CUtensorMap* m,
                                      int cx, int cy, unsigned mb) {
    asm volatile(
        "cp.async.bulk.tensor.2d.shared::cta.global.tile.mbarrier::complete_tx::bytes "
        "[%0], [%1, {%2, %3}], [%4];"
        :: "r"(dst), "l"(m), "r"(cx), "r"(cy), "r"(mb) : "memory");
}
__device__ __forceinline__ void tma2d_prefetch(const CUtensorMap* m, int cx, int cy) {
    asm volatile(
        "cp.async.bulk.prefetch.tensor.2d.L2.global.tile [%0, {%1, %2}];"
        :: "l"(m), "r"(cx), "r"(cy) : "memory");
}

// legacy cp.async (fallback kernel)
__device__ __forceinline__ void cp16(void* smem_dst, const void* gsrc) {
    asm volatile("cp.async.cg.shared.global [%0], [%1], 16;"
                 :: "r"(s2u(smem_dst)), "l"(gsrc));
}
#define CP_COMMIT() asm volatile("cp.async.commit_group;")
#define CP_WAIT(n)  asm volatile("cp.async.wait_group %0;" :: "n"(n))

// ================= TMA kernel =================
// Per-warp-private pipeline; x staged via 2x 2KB TMA box loads per 16-row tile.
// L2 prefetch runs PF_DIST chunks ahead so demand TMA completes from L2.
// SMEM tile layout per warp stage (4KB): half h (cols 32h..32h+31) at +h*2048,
// row r at +r*128, 16B unit u stored at slot u^(r&7)  (TMA SWIZZLE_128B).
__global__ void __launch_bounds__(THREADS, 4)
fused_tma_kernel(const __grid_constant__ CUtensorMap tmap,
                 const float* __restrict__ W_gen,
                 const float* __restrict__ b_gen,
                 const float* __restrict__ W_val,
                 const float* __restrict__ b_val,
                 const float* __restrict__ param,
                 const float* __restrict__ high,
                 float* __restrict__ out)
{
    __shared__ __align__(1024) float sX[4][STAGES][WR_FLTS];   // 48KB
    __shared__ unsigned long long mbar[4][STAGES];
    __shared__ float sred[32];

    const int bid  = blockIdx.x;
    const int t    = threadIdx.x;
    const int warp = t >> 5;
    const int lane = t & 31;

    const int nb    = (B_DIM - 1 - bid) / GRID + 1;     // <= 7
    const int total = nb * CH_PER_B;

    // global x row for this warp's tile of chunk i
    #define WROW(i) ((bid + ((i) >> 3) * GRID) * N_GENN + ((i) & 7) * CH_ROWS + warp * 16)

    // ---- init this warp's mbarriers
    if (lane == 0) {
        #pragma unroll
        for (int s = 0; s < STAGES; s++) mbar_init(s2u(&mbar[warp][s]), 1);
    }
    asm volatile("fence.proxy.async.shared::cta;" ::: "memory");
    __syncwarp();

    // ---- warm L2 for the first PF_DIST chunks, then issue chunks 0,1
    if (lane == 0) {
        #pragma unroll
        for (int s = 0; s < PF_DIST; s++) {
            if (s < total) {
                tma2d_prefetch(&tmap,  0, WROW(s));
                tma2d_prefetch(&tmap, 32, WROW(s));
            }
        }
        #pragma unroll
        for (int s = 0; s < 2; s++) {
            unsigned mb  = s2u(&mbar[warp][s]);
            unsigned dst = s2u(&sX[warp][s][0]);
            mbar_expect_tx(mb, 4096);
            tma2d(dst,        &tmap,  0, WROW(s), mb);
            tma2d(dst + 2048, &tmap, 32, WROW(s), mb);
        }
    }

    // ---- action-head scales
    const float s0 = 1.0f / (1.0f + expf(-param[0]));
    const float s1 = 0.5f / (1.0f + expf(-param[1]));

    // ---- B fragments (both n-tiles per warp): raw fp32 (HW truncates -> hi) + lo
    unsigned braw[2][8][2], blo[2][8][2];
    {
        const int kk = lane & 3, nn = lane >> 2;
        #pragma unroll
        for (int nt = 0; nt < 2; nt++)
            #pragma unroll
            for (int ks = 0; ks < 8; ks++)
                #pragma unroll
                for (int h = 0; h < 2; h++) {
                    float w = __ldg(&W_gen[(kk + 4 * h + 8 * ks) * EMB + nn + 8 * nt]);
                    unsigned whi = __float_as_uint(w) & 0xFFFFE000u;
                    braw[nt][ks][h] = __float_as_uint(w);
                    blo[nt][ks][h]  = __float_as_uint(w - __uint_as_float(whi));
                }
    }
    float bias[2][2];
    #pragma unroll
    for (int nt = 0; nt < 2; nt++) {
        bias[nt][0] = __ldg(&b_gen[2 * (lane & 3) + 8 * nt]);
        bias[nt][1] = __ldg(&b_gen[2 * (lane & 3) + 8 * nt + 1]);
    }

    const int hiu  = lane >> 4;
    const int r15  = lane & 15;
    const int rxor = r15 & 7;

    float vpart = 0.0f;

    #pragma unroll 1
    for (int i = 0; i < total; i++) {
        const int ch = i & 7;

        if (lane == 0) {
            if (i + PF_DIST < total) {          // keep L2 PF_DIST chunks ahead
                tma2d_prefetch(&tmap,  0, WROW(i + PF_DIST));
                tma2d_prefetch(&tmap, 32, WROW(i + PF_DIST));
            }
            if (i + 2 < total) {                // issue i+2 BEFORE waiting on i
                const int s = (i + 2) % STAGES;
                unsigned mb  = s2u(&mbar[warp][s]);
                unsigned dst = s2u(&sX[warp][s][0]);
                mbar_expect_tx(mb, 4096);
                tma2d(dst,        &tmap,  0, WROW(i + 2), mb);
                tma2d(dst + 2048, &tmap, 32, WROW(i + 2), mb);
            }
        }
        mbar_wait(s2u(&mbar[warp][i % STAGES]), (unsigned)((i / STAGES) & 1));

        if (ch == 0) {                          // action head for this batch
            float* orow = out + (size_t)(bid + (i >> 3) * GRID) * OUT_ROW;
            #pragma unroll
            for (int j = 0; j < 8; j++) {
                int idx = t + THREADS * j;
                float h = __ldg(&high[idx >> 1]);
                orow[idx] = (idx & 1) ? s1 * h : s0 * h;
            }
        }

        // C accumulators: [nt][k-parity][4]; bias into parity 0 only.
        float c[2][2][4];
        #pragma unroll
        for (int nt = 0; nt < 2; nt++) {
            c[nt][0][0] = c[nt][0][2] = bias[nt][0];
            c[nt][0][1] = c[nt][0][3] = bias[nt][1];
            c[nt][1][0] = c[nt][1][1] = c[nt][1][2] = c[nt][1][3] = 0.0f;
        }

        const unsigned sbase = s2u(&sX[warp][i % STAGES][0]) + r15 * 128;

        #pragma unroll
        for (int ks = 0; ks < 8; ks++) {
            const int U = 2 * ks + hiu;
            unsigned raw[4];
            ldsm4(raw, sbase + (U >> 3) * 2048 + (((U & 7) ^ rxor) << 4));

            unsigned alo[4];
            #pragma unroll
            for (int j = 0; j < 4; j++) {
                float x  = __uint_as_float(raw[j]);
                float hi = __uint_as_float(__float_as_uint(x) & 0xFFFFE000u);
                alo[j] = __float_as_uint(x - hi);
            }
            const int p = ks & 1;
            #pragma unroll
            for (int nt = 0; nt < 2; nt++) {
                mma_tf32(c[nt][p], alo, braw[nt][ks][0], braw[nt][ks][1]);  // lo x hi
                mma_tf32(c[nt][p], raw, blo[nt][ks][0],  blo[nt][ks][1]);   // hi x lo
                mma_tf32(c[nt][p], raw, braw[nt][ks][0], braw[nt][ks][1]);  // hi x hi
            }
        }

        // ---- Epilogue: relu + dot with W_val (L2-resident)
        const int r1 = ch * CH_ROWS + warp * 16 + (lane >> 2);
        const int r2 = r1 + 8;
        #pragma unroll
        for (int nt = 0; nt < 2; nt++) {
            const int n0 = 2 * (lane & 3) + 8 * nt;
            float2 w1 = __ldg(reinterpret_cast<const float2*>(W_val + r1 * EMB + n0));
            float2 w2 = __ldg(reinterpret_cast<const float2*>(W_val + r2 * EMB + n0));
            vpart += fmaxf(c[nt][0][0] + c[nt][1][0], 0.0f) * w1.x
                   + fmaxf(c[nt][0][1] + c[nt][1][1], 0.0f) * w1.y
                   + fmaxf(c[nt][0][2] + c[nt][1][2], 0.0f) * w2.x
                   + fmaxf(c[nt][0][3] + c[nt][1][3], 0.0f) * w2.y;
        }

        if (ch == 7) {
            #pragma unroll
            for (int o = 16; o > 0; o >>= 1)
                vpart += __shfl_down_sync(0xffffffff, vpart, o);
            if (lane == 0) sred[(i >> 3) * 4 + warp] = vpart;
            vpart = 0.0f;
        }
    }

    __syncthreads();
    if (t < nb) {
        float v = ((sred[t * 4 + 0] + sred[t * 4 + 1])
                 + (sred[t * 4 + 2] + sred[t * 4 + 3])) + b_val[0];
        out[(size_t)(bid + t * GRID) * OUT_ROW + 1024] = v;
    }
    #undef WROW
}

// ================= fallback kernel (proven R9 cp.async path) =================
#define CH_FLTS (CH_ROWS * F_GEN)

__device__ __forceinline__ void issue_warp(float* wbuf, const float* gwarp, int lane) {
    const int j = lane & 15;
    #pragma unroll
    for (int k = 0; k < 8; k++) {
        int row = 2 * k + (lane >> 4);
        int slot = j ^ (row & 7);
        cp16(&wbuf[row * 64 + slot * 4], gwarp + row * 64 + j * 4);
    }
}

__global__ void __launch_bounds__(THREADS, 4)
fused_model_kernel(const float* __restrict__ x_gen,
                   const float* __restrict__ W_gen,
                   const float* __restrict__ b_gen,
                   const float* __restrict__ W_val,
                   const float* __restrict__ b_val,
                   const float* __restrict__ param,
                   const float* __restrict__ high,
                   float* __restrict__ out)
{
    __shared__ __align__(1024) float sX[STAGES][CH_FLTS];
    __shared__ float sred[32];

    const int bid  = blockIdx.x;
    const int t    = threadIdx.x;
    const int warp = t >> 5;
    const int lane = t & 31;

    const int nb    = (B_DIM - 1 - bid) / GRID + 1;
    const int total = nb * CH_PER_B;

    #define WPTR(i) (x_gen + (size_t)(bid + ((i) >> 3) * GRID) * (N_GENN * F_GEN) \
                           + ((i) & 7) * CH_FLTS + warp * WR_FLTS)

    issue_warp(&sX[0][warp * WR_FLTS], WPTR(0), lane);   CP_COMMIT();
    issue_warp(&sX[1][warp * WR_FLTS], WPTR(1), lane);   CP_COMMIT();

    const float s0 = 1.0f / (1.0f + expf(-param[0]));
    const float s1 = 0.5f / (1.0f + expf(-param[1]));

    unsigned braw[2][8][2], blo[2][8][2];
    {
        const int kk = lane & 3, nn = lane >> 2;
        #pragma unroll
        for (int nt = 0; nt < 2; nt++)
            #pragma unroll
            for (int ks = 0; ks < 8; ks++)
                #pragma unroll
                for (int h = 0; h < 2; h++) {
                    float w = __ldg(&W_gen[(kk + 4 * h + 8 * ks) * EMB + nn + 8 * nt]);
                    unsigned whi = __float_as_uint(w) & 0xFFFFE000u;
                    braw[nt][ks][h] = __float_as_uint(w);
                    blo[nt][ks][h]  = __float_as_uint(w - __uint_as_float(whi));
                }
    }
    float bias[2][2];
    #pragma unroll
    for (int nt = 0; nt < 2; nt++) {
        bias[nt][0] = __ldg(&b_gen[2 * (lane & 3) + 8 * nt]);
        bias[nt][1] = __ldg(&b_gen[2 * (lane & 3) + 8 * nt + 1]);
    }

    const int hiu  = lane >> 4;
    const int rxor = (lane & 15) & 7;
    const unsigned lane_off = (lane & 15) * 256;

    float vpart = 0.0f;

    #pragma unroll 1
    for (int i = 0; i < total; i++) {
        const int ch = i & 7;
        if (i + 2 < total) {
            issue_warp(&sX[(i + 2) % STAGES][warp * WR_FLTS], WPTR(i + 2), lane);
            CP_COMMIT();
            CP_WAIT(2);
        } else {
            if (i == total - 2) CP_WAIT(1);
            else                CP_WAIT(0);
        }
        __syncwarp();

        if (ch == 0) {
            float* orow = out + (size_t)(bid + (i >> 3) * GRID) * OUT_ROW;
            #pragma unroll
            for (int j = 0; j < 8; j++) {
                int idx = t + THREADS * j;
                float h = __ldg(&high[idx >> 1]);
                orow[idx] = (idx & 1) ? s1 * h : s0 * h;
            }
        }

        float c[2][2][4];
        #pragma unroll
        for (int nt = 0; nt < 2; nt++) {
            c[nt][0][0] = c[nt][0][2] = bias[nt][0];
            c[nt][0][1] = c[nt][0][3] = bias[nt][1];
            c[nt][1][0] = c[nt][1][1] = c[nt][1][2] = c[nt][1][3] = 0.0f;
        }

        const unsigned sbase = s2u(&sX[i % STAGES][warp * WR_FLTS]) + lane_off;

        #pragma unroll
        for (int ks = 0; ks < 8; ks++) {
            unsigned raw[4];
            ldsm4(raw, sbase + (((2 * ks + hiu) ^ rxor) << 4));
            unsigned alo[4];
            #pragma unroll
            for (int j = 0; j < 4; j++) {
                float x  = __uint_as_float(raw[j]);
                float hi = __uint_as_float(__float_as_uint(x) & 0xFFFFE000u);
                alo[j] = __float_as_uint(x - hi);
            }
            const int p = ks & 1;
            #pragma unroll
            for (int nt = 0; nt < 2; nt++) {
                mma_tf32(c[nt][p], alo, braw[nt][ks][0], braw[nt][ks][1]);
                mma_tf32(c[nt][p], raw, blo[nt][ks][0],  blo[nt][ks][1]);
                mma_tf32(c[nt][p], raw, braw[nt][ks][0], braw[nt][ks][1]);
            }
        }

        const int r1 = ch * CH_ROWS + warp * 16 + (lane >> 2);
        const int r2 = r1 + 8;
        #pragma unroll
        for (int nt = 0; nt < 2; nt++) {
            const int n0 = 2 * (lane & 3) + 8 * nt;
            float2 w1 = __ldg(reinterpret_cast<const float2*>(W_val + r1 * EMB + n0));
            float2 w2 = __ldg(reinterpret_cast<const float2*>(W_val + r2 * EMB + n0));
            vpart += fmaxf(c[nt][0][0] + c[nt][1][0], 0.0f) * w1.x
                   + fmaxf(c[nt][0][1] + c[nt][1][1], 0.0f) * w1.y
                   + fmaxf(c[nt][0][2] + c[nt][1][2], 0.0f) * w2.x
                   + fmaxf(c[nt][0][3] + c[nt][1][3], 0.0f) * w2.y;
        }

        if (ch == 7) {
            #pragma unroll
            for (int o = 16; o > 0; o >>= 1)
                vpart += __shfl_down_sync(0xffffffff, vpart, o);
            if (lane == 0) sred[(i >> 3) * 4 + warp] = vpart;
            vpart = 0.0f;
        }
    }

    __syncthreads();
    if (t < nb) {
        float v = ((sred[t * 4 + 0] + sred[t * 4 + 1])
                 + (sred[t * 4 + 2] + sred[t * 4 + 3])) + b_val[0];
        out[(size_t)(bid + t * GRID) * OUT_ROW + 1024] = v;
    }
    #undef WPTR
}

// ================= host =================

typedef CUresult (*PFN_encodeTiled)(
    CUtensorMap*, CUtensorMapDataType, cuuint32_t, void*,
    const cuuint64_t*, const cuuint64_t*, const cuuint32_t*, const cuuint32_t*,
    CUtensorMapInterleave, CUtensorMapSwizzle, CUtensorMapL2promotion,
    CUtensorMapFloatOOBfill);

extern "C" void kernel_launch(void* const* d_in, const int* in_sizes, int n_in,
                              void* d_out, int out_size)
{
    const float* x_gen = (const float*)d_in[0];
    const float* W_gen = (const float*)d_in[1];
    const float* b_gen = (const float*)d_in[2];
    const float* W_val = (const float*)d_in[3];
    const float* b_val = (const float*)d_in[4];
    const float* param = (const float*)d_in[5];
    const float* high  = (const float*)d_in[6];
    float* out = (float*)d_out;

    static PFN_encodeTiled enc = nullptr;
    static bool probed = false;
    if (!probed) {
        probed = true;
        void* p = nullptr;
        cudaDriverEntryPointQueryResult qr;
        if (cudaGetDriverEntryPoint("cuTensorMapEncodeTiled", &p,
                                    cudaEnableDefault, &qr) == cudaSuccess &&
            qr == cudaDriverEntryPointSuccess)
            enc = (PFN_encodeTiled)p;
    }

    if (enc) {
        CUtensorMap tmap;
        cuuint64_t gdim[2]    = {F_GEN, (cuuint64_t)B_DIM * N_GENN};
        cuuint64_t gstride[1] = {F_GEN * sizeof(float)};
        cuuint32_t box[2]     = {32, 16};
        cuuint32_t estr[2]    = {1, 1};
        CUresult r = enc(&tmap, CU_TENSOR_MAP_DATA_TYPE_FLOAT32, 2, (void*)x_gen,
                         gdim, gstride, box, estr,
                         CU_TENSOR_MAP_INTERLEAVE_NONE, CU_TENSOR_MAP_SWIZZLE_128B,
                         CU_TENSOR_MAP_L2_PROMOTION_L2_128B,
                         CU_TENSOR_MAP_FLOAT_OOB_FILL_NONE);
        if (r == CUDA_SUCCESS) {
            fused_tma_kernel<<<GRID, THREADS>>>(
                tmap, W_gen, b_gen, W_val, b_val, param, high, out);
            return;
        }
    }
    fused_model_kernel<<<GRID, THREADS>>>(
        x_gen, W_gen, b_gen, W_val, b_val, param, high, out);
}

// round 12
// speedup vs baseline: 1.1257x; 1.1257x over previous
#include <cuda_runtime.h>
#include <cuda.h>
#include <math.h>

#define B_DIM   4096
#define N_GENN  512
#define F_GEN   64
#define EMB     16
#define OUT_ROW 1025
#define THREADS 128
#define CH_ROWS 64            // rows per chunk; 16 rows per warp
#define CH_PER_B 8
#define STAGES  3
#define WR_FLTS (16 * F_GEN)          // 1024 floats (4KB) per warp stage
#define GRID    608                   // 152 SMs x 4 CTAs persistent

// ---------------- shared device helpers ----------------

__device__ __forceinline__ void mma_tf32(float c[4], const unsigned a[4],
                                         unsigned b0, unsigned b1) {
    asm volatile(
        "mma.sync.aligned.m16n8k8.row.col.f32.tf32.tf32.f32 "
        "{%0,%1,%2,%3}, {%4,%5,%6,%7}, {%8,%9}, {%0,%1,%2,%3};"
        : "+f"(c[0]), "+f"(c[1]), "+f"(c[2]), "+f"(c[3])
        : "r"(a[0]), "r"(a[1]), "r"(a[2]), "r"(a[3]), "r"(b0), "r"(b1));
}

__device__ __forceinline__ void ldsm4(unsigned r[4], unsigned addr) {
    asm volatile("ldmatrix.sync.aligned.m8n8.x4.shared.b16 {%0,%1,%2,%3}, [%4];"
                 : "=r"(r[0]), "=r"(r[1]), "=r"(r[2]), "=r"(r[3]) : "r"(addr));
}

__device__ __forceinline__ unsigned s2u(const void* p) {
    return (unsigned)__cvta_generic_to_shared(p);
}

__device__ __forceinline__ void mbar_init(unsigned mb, unsigned cnt) {
    asm volatile("mbarrier.init.shared.b64 [%0], %1;" :: "r"(mb), "r"(cnt) : "memory");
}
__device__ __forceinline__ void mbar_expect_tx(unsigned mb, unsigned bytes) {
    asm volatile("mbarrier.arrive.expect_tx.shared.b64 _, [%0], %1;"
                 :: "r"(mb), "r"(bytes) : "memory");
}
__device__ __forceinline__ void mbar_wait(unsigned mb, unsigned parity) {
    asm volatile(
        "{\n\t"
        ".reg .pred P%=;\n\t"
        "W%=:\n\t"
        "mbarrier.try_wait.parity.acquire.cta.shared::cta.b64 P%=, [%0], %1, 0x989680;\n\t"
        "@P%= bra D%=;\n\t"
        "bra W%=;\n\t"
        "D%=:\n\t"
        "}"
        :: "r"(mb), "r"(parity) : "memory");
}
__device__ __forceinline__ void tma2d(unsigned dst, const CUtensorMap* m,
                                      int cx, int cy, unsigned mb) {
    asm volatile(
        "cp.async.bulk.tensor.2d.shared::cta.global.tile.mbarrier::complete_tx::bytes "
        "[%0], [%1, {%2, %3}], [%4];"
        :: "r"(dst), "l"(m), "r"(cx), "r"(cy), "r"(mb) : "memory");
}

// legacy cp.async (fallback kernel)
__device__ __forceinline__ void cp16(void* smem_dst, const void* gsrc) {
    asm volatile("cp.async.cg.shared.global [%0], [%1], 16;"
                 :: "r"(s2u(smem_dst)), "l"(gsrc));
}
#define CP_COMMIT() asm volatile("cp.async.commit_group;")
#define CP_WAIT(n)  asm volatile("cp.async.wait_group %0;" :: "n"(n))

// ================= TMA kernel =================
// Per-warp-private pipeline; x staged via 2x 2KB TMA box loads per 16-row tile,
// each half tracked by its OWN mbarrier so compute starts when half A lands.
// SMEM tile layout per warp stage (4KB): half h (cols 32h..32h+31) at +h*2048,
// row r at +r*128, 16B unit u stored at slot u^(r&7)  (TMA SWIZZLE_128B).
__global__ void __launch_bounds__(THREADS, 4)
fused_tma_kernel(const __grid_constant__ CUtensorMap tmap,
                 const float* __restrict__ W_gen,
                 const float* __restrict__ b_gen,
                 const float* __restrict__ W_val,
                 const float* __restrict__ b_val,
                 const float* __restrict__ param,
                 const float* __restrict__ high,
                 float* __restrict__ out)
{
    __shared__ __align__(1024) float sX[4][STAGES][WR_FLTS];   // 48KB
    __shared__ unsigned long long mbar[4][STAGES][2];          // per half
    __shared__ float sred[32];

    const int bid  = blockIdx.x;
    const int t    = threadIdx.x;
    const int warp = t >> 5;
    const int lane = t & 31;

    const int nb    = (B_DIM - 1 - bid) / GRID + 1;     // <= 7
    const int total = nb * CH_PER_B;

    // global x row for this warp's tile of chunk i
    #define WROW(i) ((bid + ((i) >> 3) * GRID) * N_GENN + ((i) & 7) * CH_ROWS + warp * 16)

    // ---- init this warp's mbarriers
    if (lane == 0) {
        #pragma unroll
        for (int s = 0; s < STAGES; s++) {
            mbar_init(s2u(&mbar[warp][s][0]), 1);
            mbar_init(s2u(&mbar[warp][s][1]), 1);
        }
    }
    asm volatile("fence.proxy.async.shared::cta;" ::: "memory");
    __syncwarp();

    // ---- issue chunks 0,1 (prefetch distance 2); issue-before-wait preserved
    #pragma unroll
    for (int s = 0; s < 2; s++) {
        if (lane == 0) {
            unsigned mb0 = s2u(&mbar[warp][s][0]);
            unsigned mb1 = s2u(&mbar[warp][s][1]);
            unsigned dst = s2u(&sX[warp][s][0]);
            mbar_expect_tx(mb0, 2048);
            tma2d(dst,        &tmap,  0, WROW(s), mb0);
            mbar_expect_tx(mb1, 2048);
            tma2d(dst + 2048, &tmap, 32, WROW(s), mb1);
        }
    }

    // ---- action-head scales
    const float s0 = 1.0f / (1.0f + expf(-param[0]));
    const float s1 = 0.5f / (1.0f + expf(-param[1]));

    // ---- B fragments (both n-tiles per warp): raw fp32 (HW truncates -> hi) + lo
    unsigned braw[2][8][2], blo[2][8][2];
    {
        const int kk = lane & 3, nn = lane >> 2;
        #pragma unroll
        for (int nt = 0; nt < 2; nt++)
            #pragma unroll
            for (int ks = 0; ks < 8; ks++)
                #pragma unroll
                for (int h = 0; h < 2; h++) {
                    float w = __ldg(&W_gen[(kk + 4 * h + 8 * ks) * EMB + nn + 8 * nt]);
                    unsigned whi = __float_as_uint(w) & 0xFFFFE000u;
                    braw[nt][ks][h] = __float_as_uint(w);
                    blo[nt][ks][h]  = __float_as_uint(w - __uint_as_float(whi));
                }
    }
    float bias[2][2];
    #pragma unroll
    for (int nt = 0; nt < 2; nt++) {
        bias[nt][0] = __ldg(&b_gen[2 * (lane & 3) + 8 * nt]);
        bias[nt][1] = __ldg(&b_gen[2 * (lane & 3) + 8 * nt + 1]);
    }

    const int hiu  = lane >> 4;
    const int r15  = lane & 15;
    const int rxor = r15 & 7;

    float vpart = 0.0f;

    #pragma unroll 1
    for (int i = 0; i < total; i++) {
        const int ch = i & 7;

        if (i + 2 < total && lane == 0) {       // issue i+2 BEFORE waiting on i
            const int s = (i + 2) % STAGES;
            unsigned mb0 = s2u(&mbar[warp][s][0]);
            unsigned mb1 = s2u(&mbar[warp][s][1]);
            unsigned dst = s2u(&sX[warp][s][0]);
            mbar_expect_tx(mb0, 2048);
            tma2d(dst,        &tmap,  0, WROW(i + 2), mb0);
            mbar_expect_tx(mb1, 2048);
            tma2d(dst + 2048, &tmap, 32, WROW(i + 2), mb1);
        }

        if (ch == 0) {                          // action head: batch-independent,
            float* orow = out + (size_t)(bid + (i >> 3) * GRID) * OUT_ROW;
            #pragma unroll                      // overlaps the data wait below
            for (int j = 0; j < 8; j++) {
                int idx = t + THREADS * j;
                float h = __ldg(&high[idx >> 1]);
                orow[idx] = (idx & 1) ? s1 * h : s0 * h;
            }
        }

        // C accumulators: [nt][k-parity][4]; bias into parity 0 only.
        float c[2][2][4];
        #pragma unroll
        for (int nt = 0; nt < 2; nt++) {
            c[nt][0][0] = c[nt][0][2] = bias[nt][0];
            c[nt][0][1] = c[nt][0][3] = bias[nt][1];
            c[nt][1][0] = c[nt][1][1] = c[nt][1][2] = c[nt][1][3] = 0.0f;
        }

        const unsigned sbase = s2u(&sX[warp][i % STAGES][0]) + r15 * 128;
        const unsigned par   = (unsigned)((i / STAGES) & 1);

        // ---- half A (cols 0-31): k-steps 0-3 touch 16B units U=0..7 only
        mbar_wait(s2u(&mbar[warp][i % STAGES][0]), par);

        #pragma unroll
        for (int ks = 0; ks < 8; ks++) {
            if (ks == 4)    // ---- half B (cols 32-63): U=8..15
                mbar_wait(s2u(&mbar[warp][i % STAGES][1]), par);

            const int U = 2 * ks + hiu;
            unsigned raw[4];
            ldsm4(raw, sbase + (U >> 3) * 2048 + (((U & 7) ^ rxor) << 4));

            unsigned alo[4];
            #pragma unroll
            for (int j = 0; j < 4; j++) {
                float x  = __uint_as_float(raw[j]);
                float hi = __uint_as_float(__float_as_uint(x) & 0xFFFFE000u);
                alo[j] = __float_as_uint(x - hi);
            }
            const int p = ks & 1;
            #pragma unroll
            for (int nt = 0; nt < 2; nt++) {
                mma_tf32(c[nt][p], alo, braw[nt][ks][0], braw[nt][ks][1]);  // lo x hi
                mma_tf32(c[nt][p], raw, blo[nt][ks][0],  blo[nt][ks][1]);   // hi x lo
                mma_tf32(c[nt][p], raw, braw[nt][ks][0], braw[nt][ks][1]);  // hi x hi
            }
        }

        // ---- Epilogue: relu + dot with W_val (L2-resident)
        const int r1 = ch * CH_ROWS + warp * 16 + (lane >> 2);
        const int r2 = r1 + 8;
        #pragma unroll
        for (int nt = 0; nt < 2; nt++) {
            const int n0 = 2 * (lane & 3) + 8 * nt;
            float2 w1 = __ldg(reinterpret_cast<const float2*>(W_val + r1 * EMB + n0));
            float2 w2 = __ldg(reinterpret_cast<const float2*>(W_val + r2 * EMB + n0));
            vpart += fmaxf(c[nt][0][0] + c[nt][1][0], 0.0f) * w1.x
                   + fmaxf(c[nt][0][1] + c[nt][1][1], 0.0f) * w1.y
                   + fmaxf(c[nt][0][2] + c[nt][1][2], 0.0f) * w2.x
                   + fmaxf(c[nt][0][3] + c[nt][1][3], 0.0f) * w2.y;
        }

        if (ch == 7) {
            #pragma unroll
            for (int o = 16; o > 0; o >>= 1)
                vpart += __shfl_down_sync(0xffffffff, vpart, o);
            if (lane == 0) sred[(i >> 3) * 4 + warp] = vpart;
            vpart = 0.0f;
        }
    }

    __syncthreads();
    if (t < nb) {
        float v = ((sred[t * 4 + 0] + sred[t * 4 + 1])
                 + (sred[t * 4 + 2] + sred[t * 4 + 3])) + b_val[0];
        out[(size_t)(bid + t * GRID) * OUT_ROW + 1024] = v;
    }
    #undef WROW
}

// ================= fallback kernel (proven R9 cp.async path) =================
#define CH_FLTS (CH_ROWS * F_GEN)

__device__ __forceinline__ void issue_warp(float* wbuf, const float* gwarp, int lane) {
    const int j = lane & 15;
    #pragma unroll
    for (int k = 0; k < 8; k++) {
        int row = 2 * k + (lane >> 4);
        int slot = j ^ (row & 7);
        cp16(&wbuf[row * 64 + slot * 4], gwarp + row * 64 + j * 4);
    }
}

__global__ void __launch_bounds__(THREADS, 4)
fused_model_kernel(const float* __restrict__ x_gen,
                   const float* __restrict__ W_gen,
                   const float* __restrict__ b_gen,
                   const float* __restrict__ W_val,
                   const float* __restrict__ b_val,
                   const float* __restrict__ param,
                   const float* __restrict__ high,
                   float* __restrict__ out)
{
    __shared__ __align__(1024) float sX[STAGES][CH_FLTS];
    __shared__ float sred[32];

    const int bid  = blockIdx.x;
    const int t    = threadIdx.x;
    const int warp = t >> 5;
    const int lane = t & 31;

    const int nb    = (B_DIM - 1 - bid) / GRID + 1;
    const int total = nb * CH_PER_B;

    #define WPTR(i) (x_gen + (size_t)(bid + ((i) >> 3) * GRID) * (N_GENN * F_GEN) \
                           + ((i) & 7) * CH_FLTS + warp * WR_FLTS)

    issue_warp(&sX[0][warp * WR_FLTS], WPTR(0), lane);   CP_COMMIT();
    issue_warp(&sX[1][warp * WR_FLTS], WPTR(1), lane);   CP_COMMIT();

    const float s0 = 1.0f / (1.0f + expf(-param[0]));
    const float s1 = 0.5f / (1.0f + expf(-param[1]));

    unsigned braw[2][8][2], blo[2][8][2];
    {
        const int kk = lane & 3, nn = lane >> 2;
        #pragma unroll
        for (int nt = 0; nt < 2; nt++)
            #pragma unroll
            for (int ks = 0; ks < 8; ks++)
                #pragma unroll
                for (int h = 0; h < 2; h++) {
                    float w = __ldg(&W_gen[(kk + 4 * h + 8 * ks) * EMB + nn + 8 * nt]);
                    unsigned whi = __float_as_uint(w) & 0xFFFFE000u;
                    braw[nt][ks][h] = __float_as_uint(w);
                    blo[nt][ks][h]  = __float_as_uint(w - __uint_as_float(whi));
                }
    }
    float bias[2][2];
    #pragma unroll
    for (int nt = 0; nt < 2; nt++) {
        bias[nt][0] = __ldg(&b_gen[2 * (lane & 3) + 8 * nt]);
        bias[nt][1] = __ldg(&b_gen[2 * (lane & 3) + 8 * nt + 1]);
    }

    const int hiu  = lane >> 4;
    const int rxor = (lane & 15) & 7;
    const unsigned lane_off = (lane & 15) * 256;

    float vpart = 0.0f;

    #pragma unroll 1
    for (int i = 0; i < total; i++) {
        const int ch = i & 7;
        if (i + 2 < total) {
            issue_warp(&sX[(i + 2) % STAGES][warp * WR_FLTS], WPTR(i + 2), lane);
            CP_COMMIT();
            CP_WAIT(2);
        } else {
            if (i == total - 2) CP_WAIT(1);
            else                CP_WAIT(0);
        }
        __syncwarp();

        if (ch == 0) {
            float* orow = out + (size_t)(bid + (i >> 3) * GRID) * OUT_ROW;
            #pragma unroll
            for (int j = 0; j < 8; j++) {
                int idx = t + THREADS * j;
                float h = __ldg(&high[idx >> 1]);
                orow[idx] = (idx & 1) ? s1 * h : s0 * h;
            }
        }

        float c[2][2][4];
        #pragma unroll
        for (int nt = 0; nt < 2; nt++) {
            c[nt][0][0] = c[nt][0][2] = bias[nt][0];
            c[nt][0][1] = c[nt][0][3] = bias[nt][1];
            c[nt][1][0] = c[nt][1][1] = c[nt][1][2] = c[nt][1][3] = 0.0f;
        }

        const unsigned sbase = s2u(&sX[i % STAGES][warp * WR_FLTS]) + lane_off;

        #pragma unroll
        for (int ks = 0; ks < 8; ks++) {
            unsigned raw[4];
            ldsm4(raw, sbase + (((2 * ks + hiu) ^ rxor) << 4));
            unsigned alo[4];
            #pragma unroll
            for (int j = 0; j < 4; j++) {
                float x  = __uint_as_float(raw[j]);
                float hi = __uint_as_float(__float_as_uint(x) & 0xFFFFE000u);
                alo[j] = __float_as_uint(x - hi);
            }
            const int p = ks & 1;
            #pragma unroll
            for (int nt = 0; nt < 2; nt++) {
                mma_tf32(c[nt][p], alo, braw[nt][ks][0], braw[nt][ks][1]);
                mma_tf32(c[nt][p], raw, blo[nt][ks][0],  blo[nt][ks][1]);
                mma_tf32(c[nt][p], raw, braw[nt][ks][0], braw[nt][ks][1]);
            }
        }

        const int r1 = ch * CH_ROWS + warp * 16 + (lane >> 2);
        const int r2 = r1 + 8;
        #pragma unroll
        for (int nt = 0; nt < 2; nt++) {
            const int n0 = 2 * (lane & 3) + 8 * nt;
            float2 w1 = __ldg(reinterpret_cast<const float2*>(W_val + r1 * EMB + n0));
            float2 w2 = __ldg(reinterpret_cast<const float2*>(W_val + r2 * EMB + n0));
            vpart += fmaxf(c[nt][0][0] + c[nt][1][0], 0.0f) * w1.x
                   + fmaxf(c[nt][0][1] + c[nt][1][1], 0.0f) * w1.y
                   + fmaxf(c[nt][0][2] + c[nt][1][2], 0.0f) * w2.x
                   + fmaxf(c[nt][0][3] + c[nt][1][3], 0.0f) * w2.y;
        }

        if (ch == 7) {
            #pragma unroll
            for (int o = 16; o > 0; o >>= 1)
                vpart += __shfl_down_sync(0xffffffff, vpart, o);
            if (lane == 0) sred[(i >> 3) * 4 + warp] = vpart;
            vpart = 0.0f;
        }
    }

    __syncthreads();
    if (t < nb) {
        float v = ((sred[t * 4 + 0] + sred[t * 4 + 1])
                 + (sred[t * 4 + 2] + sred[t * 4 + 3])) + b_val[0];
        out[(size_t)(bid + t * GRID) * OUT_ROW + 1024] = v;
    }
    #undef WPTR
}

// ================= host =================

typedef CUresult (*PFN_encodeTiled)(
    CUtensorMap*, CUtensorMapDataType, cuuint32_t, void*,
    const cuuint64_t*, const cuuint64_t*, const cuuint32_t*, const cuuint32_t*,
    CUtensorMapInterleave, CUtensorMapSwizzle, CUtensorMapL2promotion,
    CUtensorMapFloatOOBfill);

extern "C" void kernel_launch(void* const* d_in, const int* in_sizes, int n_in,
                              void* d_out, int out_size)
{
    const float* x_gen = (const float*)d_in[0];
    const float* W_gen = (const float*)d_in[1];
    const float* b_gen = (const float*)d_in[2];
    const float* W_val = (const float*)d_in[3];
    const float* b_val = (const float*)d_in[4];
    const float* param = (const float*)d_in[5];
    const float* high  = (const float*)d_in[6];
    float* out = (float*)d_out;

    static PFN_encodeTiled enc = nullptr;
    static bool probed = false;
    if (!probed) {
        probed = true;
        void* p = nullptr;
        cudaDriverEntryPointQueryResult qr;
        if (cudaGetDriverEntryPoint("cuTensorMapEncodeTiled", &p,
                                    cudaEnableDefault, &qr) == cudaSuccess &&
            qr == cudaDriverEntryPointSuccess)
            enc = (PFN_encodeTiled)p;
    }

    if (enc) {
        CUtensorMap tmap;
        cuuint64_t gdim[2]    = {F_GEN, (cuuint64_t)B_DIM * N_GENN};
        cuuint64_t gstride[1] = {F_GEN * sizeof(float)};
        cuuint32_t box[2]     = {32, 16};
        cuuint32_t estr[2]    = {1, 1};
        CUresult r = enc(&tmap, CU_TENSOR_MAP_DATA_TYPE_FLOAT32, 2, (void*)x_gen,
                         gdim, gstride, box, estr,
                         CU_TENSOR_MAP_INTERLEAVE_NONE, CU_TENSOR_MAP_SWIZZLE_128B,
                         CU_TENSOR_MAP_L2_PROMOTION_L2_128B,
                         CU_TENSOR_MAP_FLOAT_OOB_FILL_NONE);
        if (r == CUDA_SUCCESS) {
            fused_tma_kernel<<<GRID, THREADS>>>(
                tmap, W_gen, b_gen, W_val, b_val, param, high, out);
            return;
        }
    }
    fused_model_kernel<<<GRID, THREADS>>>(
        x_gen, W_gen, b_gen, W_val, b_val, param, high, out);
}

// round 13
// speedup vs baseline: 1.1328x; 1.0063x over previous
#include <cuda_runtime.h>
#include <cuda.h>
#include <math.h>

#define B_DIM   4096
#define N_GENN  512
#define F_GEN   64
#define EMB     16
#define OUT_ROW 1025
#define THREADS 128
#define CH_ROWS 64            // rows per chunk; 16 rows per warp
#define CH_PER_B 8
#define STAGES  3
#define WR_FLTS (16 * F_GEN)          // 1024 floats (4KB) per warp stage
#define GRID    608                   // 152 SMs x 4 CTAs persistent

// ---------------- shared device helpers ----------------

__device__ __forceinline__ void mma_tf32(float c[4], const unsigned a[4],
                                         unsigned b0, unsigned b1) {
    asm volatile(
        "mma.sync.aligned.m16n8k8.row.col.f32.tf32.tf32.f32 "
        "{%0,%1,%2,%3}, {%4,%5,%6,%7}, {%8,%9}, {%0,%1,%2,%3};"
        : "+f"(c[0]), "+f"(c[1]), "+f"(c[2]), "+f"(c[3])
        : "r"(a[0]), "r"(a[1]), "r"(a[2]), "r"(a[3]), "r"(b0), "r"(b1));
}

__device__ __forceinline__ void ldsm4(unsigned r[4], unsigned addr) {
    asm volatile("ldmatrix.sync.aligned.m8n8.x4.shared.b16 {%0,%1,%2,%3}, [%4];"
                 : "=r"(r[0]), "=r"(r[1]), "=r"(r[2]), "=r"(r[3]) : "r"(addr));
}

__device__ __forceinline__ unsigned s2u(const void* p) {
    return (unsigned)__cvta_generic_to_shared(p);
}

__device__ __forceinline__ void mbar_init(unsigned mb, unsigned cnt) {
    asm volatile("mbarrier.init.shared.b64 [%0], %1;" :: "r"(mb), "r"(cnt) : "memory");
}
__device__ __forceinline__ void mbar_expect_tx(unsigned mb, unsigned bytes) {
    asm volatile("mbarrier.arrive.expect_tx.shared.b64 _, [%0], %1;"
                 :: "r"(mb), "r"(bytes) : "memory");
}
__device__ __forceinline__ void mbar_wait(unsigned mb, unsigned parity) {
    asm volatile(
        "{\n\t"
        ".reg .pred P%=;\n\t"
        "W%=:\n\t"
        "mbarrier.try_wait.parity.acquire.cta.shared::cta.b64 P%=, [%0], %1, 0x989680;\n\t"
        "@P%= bra D%=;\n\t"
        "bra W%=;\n\t"
        "D%=:\n\t"
        "}"
        :: "r"(mb), "r"(parity) : "memory");
}
__device__ __forceinline__ void tma2d(unsigned dst, const CUtensorMap* m,
                                      int cx, int cy, unsigned mb) {
    asm volatile(
        "cp.async.bulk.tensor.2d.shared::cta.global.tile.mbarrier::complete_tx::bytes "
        "[%0], [%1, {%2, %3}], [%4];"
        :: "r"(dst), "l"(m), "r"(cx), "r"(cy), "r"(mb) : "memory");
}

// legacy cp.async (fallback kernel)
__device__ __forceinline__ void cp16(void* smem_dst, const void* gsrc) {
    asm volatile("cp.async.cg.shared.global [%0], [%1], 16;"
                 :: "r"(s2u(smem_dst)), "l"(gsrc));
}
#define CP_COMMIT() asm volatile("cp.async.commit_group;")
#define CP_WAIT(n)  asm volatile("cp.async.wait_group %0;" :: "n"(n))

// ================= TMA kernel =================
// Per-warp-private pipeline (R10 load schedule, byte-identical).
// Register diet: blo recomputed per use; W_val + action head prefetched
// BEFORE the mbarrier wait so their latency hides under the data wait.
__global__ void __launch_bounds__(THREADS, 4)
fused_tma_kernel(const __grid_constant__ CUtensorMap tmap,
                 const float* __restrict__ W_gen,
                 const float* __restrict__ b_gen,
                 const float* __restrict__ W_val,
                 const float* __restrict__ b_val,
                 const float* __restrict__ param,
                 const float* __restrict__ high,
                 float* __restrict__ out)
{
    __shared__ __align__(1024) float sX[4][STAGES][WR_FLTS];   // 48KB
    __shared__ unsigned long long mbar[4][STAGES];
    __shared__ float sred[32];

    const int bid  = blockIdx.x;
    const int t    = threadIdx.x;
    const int warp = t >> 5;
    const int lane = t & 31;

    const int nb    = (B_DIM - 1 - bid) / GRID + 1;     // <= 7
    const int total = nb * CH_PER_B;

    // global x row for this warp's tile of chunk i
    #define WROW(i) ((bid + ((i) >> 3) * GRID) * N_GENN + ((i) & 7) * CH_ROWS + warp * 16)

    // ---- init this warp's mbarriers
    if (lane == 0) {
        #pragma unroll
        for (int s = 0; s < STAGES; s++) mbar_init(s2u(&mbar[warp][s]), 1);
    }
    asm volatile("fence.proxy.async.shared::cta;" ::: "memory");
    __syncwarp();

    // ---- issue chunks 0,1 (prefetch distance 2); issue-before-wait preserved
    #pragma unroll
    for (int s = 0; s < 2; s++) {
        if (lane == 0) {
            unsigned mb  = s2u(&mbar[warp][s]);
            unsigned dst = s2u(&sX[warp][s][0]);
            mbar_expect_tx(mb, 4096);
            tma2d(dst,        &tmap,  0, WROW(s), mb);
            tma2d(dst + 2048, &tmap, 32, WROW(s), mb);
        }
    }

    // ---- action-head scales
    const float s0 = 1.0f / (1.0f + expf(-param[0]));
    const float s1 = 0.5f / (1.0f + expf(-param[1]));

    // ---- B fragments: raw fp32 only (HW truncates to tf32 = hi); lo recomputed
    //      per use (w - trunc(w), bit-identical to a stored lo). 32 regs.
    unsigned braw[2][8][2];
    {
        const int kk = lane & 3, nn = lane >> 2;
        #pragma unroll
        for (int nt = 0; nt < 2; nt++)
            #pragma unroll
            for (int ks = 0; ks < 8; ks++)
                #pragma unroll
                for (int h = 0; h < 2; h++)
                    braw[nt][ks][h] = __float_as_uint(
                        __ldg(&W_gen[(kk + 4 * h + 8 * ks) * EMB + nn + 8 * nt]));
    }
    float bias[2][2];
    #pragma unroll
    for (int nt = 0; nt < 2; nt++) {
        bias[nt][0] = __ldg(&b_gen[2 * (lane & 3) + 8 * nt]);
        bias[nt][1] = __ldg(&b_gen[2 * (lane & 3) + 8 * nt + 1]);
    }

    const int hiu  = lane >> 4;
    const int r15  = lane & 15;
    const int rxor = r15 & 7;

    float vpart = 0.0f;

    #pragma unroll 1
    for (int i = 0; i < total; i++) {
        const int ch = i & 7;

        if (i + 2 < total && lane == 0) {       // issue i+2 BEFORE waiting on i
            const int s = (i + 2) % STAGES;
            unsigned mb  = s2u(&mbar[warp][s]);
            unsigned dst = s2u(&sX[warp][s][0]);
            mbar_expect_tx(mb, 4096);
            tma2d(dst,        &tmap,  0, WROW(i + 2), mb);
            tma2d(dst + 2048, &tmap, 32, WROW(i + 2), mb);
        }

        // ---- Pre-wait overlap work (no dependence on chunk i's data):
        // 1) W_val prefetch for this chunk's epilogue (L2 latency hides here)
        const int r1 = ch * CH_ROWS + warp * 16 + (lane >> 2);
        const int r2 = r1 + 8;
        float2 wv1[2], wv2[2];
        #pragma unroll
        for (int nt = 0; nt < 2; nt++) {
            const int n0 = 2 * (lane & 3) + 8 * nt;
            wv1[nt] = __ldg(reinterpret_cast<const float2*>(W_val + r1 * EMB + n0));
            wv2[nt] = __ldg(reinterpret_cast<const float2*>(W_val + r2 * EMB + n0));
        }
        // 2) action head for this batch (batch-independent stores)
        if (ch == 0) {
            float* orow = out + (size_t)(bid + (i >> 3) * GRID) * OUT_ROW;
            #pragma unroll
            for (int j = 0; j < 8; j++) {
                int idx = t + THREADS * j;
                float h = __ldg(&high[idx >> 1]);
                orow[idx] = (idx & 1) ? s1 * h : s0 * h;
            }
        }

        mbar_wait(s2u(&mbar[warp][i % STAGES]), (unsigned)((i / STAGES) & 1));

        // C accumulators: [nt][k-parity][4]; bias into parity 0 only.
        float c[2][2][4];
        #pragma unroll
        for (int nt = 0; nt < 2; nt++) {
            c[nt][0][0] = c[nt][0][2] = bias[nt][0];
            c[nt][0][1] = c[nt][0][3] = bias[nt][1];
            c[nt][1][0] = c[nt][1][1] = c[nt][1][2] = c[nt][1][3] = 0.0f;
        }

        const unsigned sbase = s2u(&sX[warp][i % STAGES][0]) + r15 * 128;

        #pragma unroll
        for (int ks = 0; ks < 8; ks++) {
            const int U = 2 * ks + hiu;
            unsigned raw[4];
            ldsm4(raw, sbase + (U >> 3) * 2048 + (((U & 7) ^ rxor) << 4));

            unsigned alo[4];
            #pragma unroll
            for (int j = 0; j < 4; j++) {
                float x  = __uint_as_float(raw[j]);
                float hi = __uint_as_float(__float_as_uint(x) & 0xFFFFE000u);
                alo[j] = __float_as_uint(x - hi);
            }
            const int p = ks & 1;
            #pragma unroll
            for (int nt = 0; nt < 2; nt++) {
                // recompute blo (bit-identical to stored): lo = w - trunc(w)
                float w0 = __uint_as_float(braw[nt][ks][0]);
                float w1 = __uint_as_float(braw[nt][ks][1]);
                unsigned bl0 = __float_as_uint(
                    w0 - __uint_as_float(braw[nt][ks][0] & 0xFFFFE000u));
                unsigned bl1 = __float_as_uint(
                    w1 - __uint_as_float(braw[nt][ks][1] & 0xFFFFE000u));
                mma_tf32(c[nt][p], alo, braw[nt][ks][0], braw[nt][ks][1]);  // lo x hi
                mma_tf32(c[nt][p], raw, bl0, bl1);                          // hi x lo
                mma_tf32(c[nt][p], raw, braw[nt][ks][0], braw[nt][ks][1]);  // hi x hi
            }
        }

        // ---- Epilogue: relu + dot with prefetched W_val (no memory stall)
        #pragma unroll
        for (int nt = 0; nt < 2; nt++) {
            vpart += fmaxf(c[nt][0][0] + c[nt][1][0], 0.0f) * wv1[nt].x
                   + fmaxf(c[nt][0][1] + c[nt][1][1], 0.0f) * wv1[nt].y
                   + fmaxf(c[nt][0][2] + c[nt][1][2], 0.0f) * wv2[nt].x
                   + fmaxf(c[nt][0][3] + c[nt][1][3], 0.0f) * wv2[nt].y;
        }

        if (ch == 7) {
            #pragma unroll
            for (int o = 16; o > 0; o >>= 1)
                vpart += __shfl_down_sync(0xffffffff, vpart, o);
            if (lane == 0) sred[(i >> 3) * 4 + warp] = vpart;
            vpart = 0.0f;
        }
    }

    __syncthreads();
    if (t < nb) {
        float v = ((sred[t * 4 + 0] + sred[t * 4 + 1])
                 + (sred[t * 4 + 2] + sred[t * 4 + 3])) + b_val[0];
        out[(size_t)(bid + t * GRID) * OUT_ROW + 1024] = v;
    }
    #undef WROW
}

// ================= fallback kernel (proven R9 cp.async path) =================
#define CH_FLTS (CH_ROWS * F_GEN)

__device__ __forceinline__ void issue_warp(float* wbuf, const float* gwarp, int lane) {
    const int j = lane & 15;
    #pragma unroll
    for (int k = 0; k < 8; k++) {
        int row = 2 * k + (lane >> 4);
        int slot = j ^ (row & 7);
        cp16(&wbuf[row * 64 + slot * 4], gwarp + row * 64 + j * 4);
    }
}

__global__ void __launch_bounds__(THREADS, 4)
fused_model_kernel(const float* __restrict__ x_gen,
                   const float* __restrict__ W_gen,
                   const float* __restrict__ b_gen,
                   const float* __restrict__ W_val,
                   const float* __restrict__ b_val,
                   const float* __restrict__ param,
                   const float* __restrict__ high,
                   float* __restrict__ out)
{
    __shared__ __align__(1024) float sX[STAGES][CH_FLTS];
    __shared__ float sred[32];

    const int bid  = blockIdx.x;
    const int t    = threadIdx.x;
    const int warp = t >> 5;
    const int lane = t & 31;

    const int nb    = (B_DIM - 1 - bid) / GRID + 1;
    const int total = nb * CH_PER_B;

    #define WPTR(i) (x_gen + (size_t)(bid + ((i) >> 3) * GRID) * (N_GENN * F_GEN) \
                           + ((i) & 7) * CH_FLTS + warp * WR_FLTS)

    issue_warp(&sX[0][warp * WR_FLTS], WPTR(0), lane);   CP_COMMIT();
    issue_warp(&sX[1][warp * WR_FLTS], WPTR(1), lane);   CP_COMMIT();

    const float s0 = 1.0f / (1.0f + expf(-param[0]));
    const float s1 = 0.5f / (1.0f + expf(-param[1]));

    unsigned braw[2][8][2], blo[2][8][2];
    {
        const int kk = lane & 3, nn = lane >> 2;
        #pragma unroll
        for (int nt = 0; nt < 2; nt++)
            #pragma unroll
            for (int ks = 0; ks < 8; ks++)
                #pragma unroll
                for (int h = 0; h < 2; h++) {
                    float w = __ldg(&W_gen[(kk + 4 * h + 8 * ks) * EMB + nn + 8 * nt]);
                    unsigned whi = __float_as_uint(w) & 0xFFFFE000u;
                    braw[nt][ks][h] = __float_as_uint(w);
                    blo[nt][ks][h]  = __float_as_uint(w - __uint_as_float(whi));
                }
    }
    float bias[2][2];
    #pragma unroll
    for (int nt = 0; nt < 2; nt++) {
        bias[nt][0] = __ldg(&b_gen[2 * (lane & 3) + 8 * nt]);
        bias[nt][1] = __ldg(&b_gen[2 * (lane & 3) + 8 * nt + 1]);
    }

    const int hiu  = lane >> 4;
    const int rxor = (lane & 15) & 7;
    const unsigned lane_off = (lane & 15) * 256;

    float vpart = 0.0f;

    #pragma unroll 1
    for (int i = 0; i < total; i++) {
        const int ch = i & 7;
        if (i + 2 < total) {
            issue_warp(&sX[(i + 2) % STAGES][warp * WR_FLTS], WPTR(i + 2), lane);
            CP_COMMIT();
            CP_WAIT(2);
        } else {
            if (i == total - 2) CP_WAIT(1);
            else                CP_WAIT(0);
        }
        __syncwarp();

        if (ch == 0) {
            float* orow = out + (size_t)(bid + (i >> 3) * GRID) * OUT_ROW;
            #pragma unroll
            for (int j = 0; j < 8; j++) {
                int idx = t + THREADS * j;
                float h = __ldg(&high[idx >> 1]);
                orow[idx] = (idx & 1) ? s1 * h : s0 * h;
            }
        }

        float c[2][2][4];
        #pragma unroll
        for (int nt = 0; nt < 2; nt++) {
            c[nt][0][0] = c[nt][0][2] = bias[nt][0];
            c[nt][0][1] = c[nt][0][3] = bias[nt][1];
            c[nt][1][0] = c[nt][1][1] = c[nt][1][2] = c[nt][1][3] = 0.0f;
        }

        const unsigned sbase = s2u(&sX[i % STAGES][warp * WR_FLTS]) + lane_off;

        #pragma unroll
        for (int ks = 0; ks < 8; ks++) {
            unsigned raw[4];
            ldsm4(raw, sbase + (((2 * ks + hiu) ^ rxor) << 4));
            unsigned alo[4];
            #pragma unroll
            for (int j = 0; j < 4; j++) {
                float x  = __uint_as_float(raw[j]);
                float hi = __uint_as_float(__float_as_uint(x) & 0xFFFFE000u);
                alo[j] = __float_as_uint(x - hi);
            }
            const int p = ks & 1;
            #pragma unroll
            for (int nt = 0; nt < 2; nt++) {
                mma_tf32(c[nt][p], alo, braw[nt][ks][0], braw[nt][ks][1]);
                mma_tf32(c[nt][p], raw, blo[nt][ks][0],  blo[nt][ks][1]);
                mma_tf32(c[nt][p], raw, braw[nt][ks][0], braw[nt][ks][1]);
            }
        }

        const int r1 = ch * CH_ROWS + warp * 16 + (lane >> 2);
        const int r2 = r1 + 8;
        #pragma unroll
        for (int nt = 0; nt < 2; nt++) {
            const int n0 = 2 * (lane & 3) + 8 * nt;
            float2 w1 = __ldg(reinterpret_cast<const float2*>(W_val + r1 * EMB + n0));
            float2 w2 = __ldg(reinterpret_cast<const float2*>(W_val + r2 * EMB + n0));
            vpart += fmaxf(c[nt][0][0] + c[nt][1][0], 0.0f) * w1.x
                   + fmaxf(c[nt][0][1] + c[nt][1][1], 0.0f) * w1.y
                   + fmaxf(c[nt][0][2] + c[nt][1][2], 0.0f) * w2.x
                   + fmaxf(c[nt][0][3] + c[nt][1][3], 0.0f) * w2.y;
        }

        if (ch == 7) {
            #pragma unroll
            for (int o = 16; o > 0; o >>= 1)
                vpart += __shfl_down_sync(0xffffffff, vpart, o);
            if (lane == 0) sred[(i >> 3) * 4 + warp] = vpart;
            vpart = 0.0f;
        }
    }

    __syncthreads();
    if (t < nb) {
        float v = ((sred[t * 4 + 0] + sred[t * 4 + 1])
                 + (sred[t * 4 + 2] + sred[t * 4 + 3])) + b_val[0];
        out[(size_t)(bid + t * GRID) * OUT_ROW + 1024] = v;
    }
    #undef WPTR
}

// ================= host =================

typedef CUresult (*PFN_encodeTiled)(
    CUtensorMap*, CUtensorMapDataType, cuuint32_t, void*,
    const cuuint64_t*, const cuuint64_t*, const cuuint32_t*, const cuuint32_t*,
    CUtensorMapInterleave, CUtensorMapSwizzle, CUtensorMapL2promotion,
    CUtensorMapFloatOOBfill);

extern "C" void kernel_launch(void* const* d_in, const int* in_sizes, int n_in,
                              void* d_out, int out_size)
{
    const float* x_gen = (const float*)d_in[0];
    const float* W_gen = (const float*)d_in[1];
    const float* b_gen = (const float*)d_in[2];
    const float* W_val = (const float*)d_in[3];
    const float* b_val = (const float*)d_in[4];
    const float* param = (const float*)d_in[5];
    const float* high  = (const float*)d_in[6];
    float* out = (float*)d_out;

    static PFN_encodeTiled enc = nullptr;
    static bool probed = false;
    if (!probed) {
        probed = true;
        void* p = nullptr;
        cudaDriverEntryPointQueryResult qr;
        if (cudaGetDriverEntryPoint("cuTensorMapEncodeTiled", &p,
                                    cudaEnableDefault, &qr) == cudaSuccess &&
            qr == cudaDriverEntryPointSuccess)
            enc = (PFN_encodeTiled)p;
    }

    if (enc) {
        CUtensorMap tmap;
        cuuint64_t gdim[2]    = {F_GEN, (cuuint64_t)B_DIM * N_GENN};
        cuuint64_t gstride[1] = {F_GEN * sizeof(float)};
        cuuint32_t box[2]     = {32, 16};
        cuuint32_t estr[2]    = {1, 1};
        CUresult r = enc(&tmap, CU_TENSOR_MAP_DATA_TYPE_FLOAT32, 2, (void*)x_gen,
                         gdim, gstride, box, estr,
                         CU_TENSOR_MAP_INTERLEAVE_NONE, CU_TENSOR_MAP_SWIZZLE_128B,
                         CU_TENSOR_MAP_L2_PROMOTION_L2_128B,
                         CU_TENSOR_MAP_FLOAT_OOB_FILL_NONE);
        if (r == CUDA_SUCCESS) {
            fused_tma_kernel<<<GRID, THREADS>>>(
                tmap, W_gen, b_gen, W_val, b_val, param, high, out);
            return;
        }
    }
    fused_model_kernel<<<GRID, THREADS>>>(
        x_gen, W_gen, b_gen, W_val, b_val, param, high, out);
}

// round 14
// speedup vs baseline: 1.1581x; 1.0223x over previous
#include <cuda_runtime.h>
#include <cuda.h>
#include <math.h>

#define B_DIM   4096
#define N_GENN  512
#define F_GEN   64
#define EMB     16
#define OUT_ROW 1025
#define THREADS 128
#define CH_ROWS 64            // rows per chunk; 16 rows per warp
#define CH_PER_B 8
#define STAGES  4             // PD=3: deeper per-warp pipeline
#define WR_FLTS (16 * F_GEN)          // 1024 floats (4KB) per warp stage
#define GRID    456                   // 152 SMs x 3 CTAs persistent (192KB smem/SM)

// dynamic smem: sX[4 warps][4 stages][1024 floats] | mbar[4][4] u64 | sred[40]
#define SMEM_X_FLTS   (4 * STAGES * WR_FLTS)                 // 16384 floats
#define SMEM_BYTES    (SMEM_X_FLTS * 4 + 4 * STAGES * 8 + 40 * 4)

// ---------------- shared device helpers ----------------

__device__ __forceinline__ void mma_tf32(float c[4], const unsigned a[4],
                                         unsigned b0, unsigned b1) {
    asm volatile(
        "mma.sync.aligned.m16n8k8.row.col.f32.tf32.tf32.f32 "
        "{%0,%1,%2,%3}, {%4,%5,%6,%7}, {%8,%9}, {%0,%1,%2,%3};"
        : "+f"(c[0]), "+f"(c[1]), "+f"(c[2]), "+f"(c[3])
        : "r"(a[0]), "r"(a[1]), "r"(a[2]), "r"(a[3]), "r"(b0), "r"(b1));
}

__device__ __forceinline__ void ldsm4(unsigned r[4], unsigned addr) {
    asm volatile("ldmatrix.sync.aligned.m8n8.x4.shared.b16 {%0,%1,%2,%3}, [%4];"
                 : "=r"(r[0]), "=r"(r[1]), "=r"(r[2]), "=r"(r[3]) : "r"(addr));
}

__device__ __forceinline__ unsigned s2u(const void* p) {
    return (unsigned)__cvta_generic_to_shared(p);
}

__device__ __forceinline__ void mbar_init(unsigned mb, unsigned cnt) {
    asm volatile("mbarrier.init.shared.b64 [%0], %1;" :: "r"(mb), "r"(cnt) : "memory");
}
__device__ __forceinline__ void mbar_expect_tx(unsigned mb, unsigned bytes) {
    asm volatile("mbarrier.arrive.expect_tx.shared.b64 _, [%0], %1;"
                 :: "r"(mb), "r"(bytes) : "memory");
}
__device__ __forceinline__ void mbar_wait(unsigned mb, unsigned parity) {
    asm volatile(
        "{\n\t"
        ".reg .pred P%=;\n\t"
        "W%=:\n\t"
        "mbarrier.try_wait.parity.acquire.cta.shared::cta.b64 P%=, [%0], %1, 0x989680;\n\t"
        "@P%= bra D%=;\n\t"
        "bra W%=;\n\t"
        "D%=:\n\t"
        "}"
        :: "r"(mb), "r"(parity) : "memory");
}
__device__ __forceinline__ void tma2d(unsigned dst, const CUtensorMap* m,
                                      int cx, int cy, unsigned mb) {
    asm volatile(
        "cp.async.bulk.tensor.2d.shared::cta.global.tile.mbarrier::complete_tx::bytes "
        "[%0], [%1, {%2, %3}], [%4];"
        :: "r"(dst), "l"(m), "r"(cx), "r"(cy), "r"(mb) : "memory");
}

// legacy cp.async (fallback kernel)
__device__ __forceinline__ void cp16(void* smem_dst, const void* gsrc) {
    asm volatile("cp.async.cg.shared.global [%0], [%1], 16;"
                 :: "r"(s2u(smem_dst)), "l"(gsrc));
}
#define CP_COMMIT() asm volatile("cp.async.commit_group;")
#define CP_WAIT(n)  asm volatile("cp.async.wait_group %0;" :: "n"(n))

// ================= TMA kernel =================
// Per-warp-private pipeline (issue-before-wait preserved), 4 stages / PD=3.
// SMEM tile layout per warp stage (4KB): half h (cols 32h..32h+31) at +h*2048,
// row r at +r*128, 16B unit u stored at slot u^(r&7)  (TMA SWIZZLE_128B).
extern __shared__ float smem_dyn[];

__global__ void __launch_bounds__(THREADS, 3)
fused_tma_kernel(const __grid_constant__ CUtensorMap tmap,
                 const float* __restrict__ W_gen,
                 const float* __restrict__ b_gen,
                 const float* __restrict__ W_val,
                 const float* __restrict__ b_val,
                 const float* __restrict__ param,
                 const float* __restrict__ high,
                 float* __restrict__ out)
{
    float* sX = smem_dyn;                                    // [warp*STAGES+s]*1024
    unsigned long long* mbar =
        reinterpret_cast<unsigned long long*>(smem_dyn + SMEM_X_FLTS);  // [warp*STAGES+s]
    float* sred = reinterpret_cast<float*>(mbar + 4 * STAGES);          // [40]

    const int bid  = blockIdx.x;
    const int t    = threadIdx.x;
    const int warp = t >> 5;
    const int lane = t & 31;

    const int nb    = (B_DIM - 1 - bid) / GRID + 1;     // <= 9
    const int total = nb * CH_PER_B;

    // global x row for this warp's tile of chunk i
    #define WROW(i) ((bid + ((i) >> 3) * GRID) * N_GENN + ((i) & 7) * CH_ROWS + warp * 16)
    #define WBUF(s) (sX + (warp * STAGES + (s)) * WR_FLTS)
    #define WMB(s)  (&mbar[warp * STAGES + (s)])

    // ---- init this warp's mbarriers
    if (lane == 0) {
        #pragma unroll
        for (int s = 0; s < STAGES; s++) mbar_init(s2u(WMB(s)), 1);
    }
    asm volatile("fence.proxy.async.shared::cta;" ::: "memory");
    __syncwarp();

    // ---- issue chunks 0..2 (prefetch distance 3); issue-before-wait preserved
    #pragma unroll
    for (int s = 0; s < 3; s++) {
        if (lane == 0 && s < total) {
            unsigned mb  = s2u(WMB(s));
            unsigned dst = s2u(WBUF(s));
            mbar_expect_tx(mb, 4096);
            tma2d(dst,        &tmap,  0, WROW(s), mb);
            tma2d(dst + 2048, &tmap, 32, WROW(s), mb);
        }
    }

    // ---- action-head scales
    const float s0 = 1.0f / (1.0f + expf(-param[0]));
    const float s1 = 0.5f / (1.0f + expf(-param[1]));

    // ---- B fragments (both n-tiles per warp): raw fp32 (HW truncates -> hi) + lo
    unsigned braw[2][8][2], blo[2][8][2];
    {
        const int kk = lane & 3, nn = lane >> 2;
        #pragma unroll
        for (int nt = 0; nt < 2; nt++)
            #pragma unroll
            for (int ks = 0; ks < 8; ks++)
                #pragma unroll
                for (int h = 0; h < 2; h++) {
                    float w = __ldg(&W_gen[(kk + 4 * h + 8 * ks) * EMB + nn + 8 * nt]);
                    unsigned whi = __float_as_uint(w) & 0xFFFFE000u;
                    braw[nt][ks][h] = __float_as_uint(w);
                    blo[nt][ks][h]  = __float_as_uint(w - __uint_as_float(whi));
                }
    }
    float bias[2][2];
    #pragma unroll
    for (int nt = 0; nt < 2; nt++) {
        bias[nt][0] = __ldg(&b_gen[2 * (lane & 3) + 8 * nt]);
        bias[nt][1] = __ldg(&b_gen[2 * (lane & 3) + 8 * nt + 1]);
    }

    const int hiu  = lane >> 4;
    const int r15  = lane & 15;
    const int rxor = r15 & 7;

    float vpart = 0.0f;

    #pragma unroll 1
    for (int i = 0; i < total; i++) {
        const int ch = i & 7;

        if (i + 3 < total && lane == 0) {       // issue i+3 BEFORE waiting on i
            const int s = (i + 3) % STAGES;
            unsigned mb  = s2u(WMB(s));
            unsigned dst = s2u(WBUF(s));
            mbar_expect_tx(mb, 4096);
            tma2d(dst,        &tmap,  0, WROW(i + 3), mb);
            tma2d(dst + 2048, &tmap, 32, WROW(i + 3), mb);
        }

        // ---- Pre-wait overlap work (no dependence on chunk i's data)
        const int r1 = ch * CH_ROWS + warp * 16 + (lane >> 2);
        const int r2 = r1 + 8;
        float2 wv1[2], wv2[2];
        #pragma unroll
        for (int nt = 0; nt < 2; nt++) {
            const int n0 = 2 * (lane & 3) + 8 * nt;
            wv1[nt] = __ldg(reinterpret_cast<const float2*>(W_val + r1 * EMB + n0));
            wv2[nt] = __ldg(reinterpret_cast<const float2*>(W_val + r2 * EMB + n0));
        }
        if (ch == 0) {                          // action head for this batch
            float* orow = out + (size_t)(bid + (i >> 3) * GRID) * OUT_ROW;
            #pragma unroll
            for (int j = 0; j < 8; j++) {
                int idx = t + THREADS * j;
                float h = __ldg(&high[idx >> 1]);
                orow[idx] = (idx & 1) ? s1 * h : s0 * h;
            }
        }

        mbar_wait(s2u(WMB(i % STAGES)), (unsigned)((i >> 2) & 1));

        // C accumulators: [nt][k-parity][4]; bias into parity 0 only.
        float c[2][2][4];
        #pragma unroll
        for (int nt = 0; nt < 2; nt++) {
            c[nt][0][0] = c[nt][0][2] = bias[nt][0];
            c[nt][0][1] = c[nt][0][3] = bias[nt][1];
            c[nt][1][0] = c[nt][1][1] = c[nt][1][2] = c[nt][1][3] = 0.0f;
        }

        const unsigned sbase = s2u(WBUF(i % STAGES)) + r15 * 128;

        #pragma unroll
        for (int ks = 0; ks < 8; ks++) {
            const int U = 2 * ks + hiu;
            unsigned raw[4];
            ldsm4(raw, sbase + (U >> 3) * 2048 + (((U & 7) ^ rxor) << 4));

            unsigned alo[4];
            #pragma unroll
            for (int j = 0; j < 4; j++) {
                float x  = __uint_as_float(raw[j]);
                float hi = __uint_as_float(__float_as_uint(x) & 0xFFFFE000u);
                alo[j] = __float_as_uint(x - hi);
            }
            const int p = ks & 1;
            #pragma unroll
            for (int nt = 0; nt < 2; nt++) {
                mma_tf32(c[nt][p], alo, braw[nt][ks][0], braw[nt][ks][1]);  // lo x hi
                mma_tf32(c[nt][p], raw, blo[nt][ks][0],  blo[nt][ks][1]);   // hi x lo
                mma_tf32(c[nt][p], raw, braw[nt][ks][0], braw[nt][ks][1]);  // hi x hi
            }
        }

        // ---- Epilogue: relu + dot with prefetched W_val
        #pragma unroll
        for (int nt = 0; nt < 2; nt++) {
            vpart += fmaxf(c[nt][0][0] + c[nt][1][0], 0.0f) * wv1[nt].x
                   + fmaxf(c[nt][0][1] + c[nt][1][1], 0.0f) * wv1[nt].y
                   + fmaxf(c[nt][0][2] + c[nt][1][2], 0.0f) * wv2[nt].x
                   + fmaxf(c[nt][0][3] + c[nt][1][3], 0.0f) * wv2[nt].y;
        }

        if (ch == 7) {
            #pragma unroll
            for (int o = 16; o > 0; o >>= 1)
                vpart += __shfl_down_sync(0xffffffff, vpart, o);
            if (lane == 0) sred[(i >> 3) * 4 + warp] = vpart;
            vpart = 0.0f;
        }
    }

    __syncthreads();
    if (t < nb) {
        float v = ((sred[t * 4 + 0] + sred[t * 4 + 1])
                 + (sred[t * 4 + 2] + sred[t * 4 + 3])) + b_val[0];
        out[(size_t)(bid + t * GRID) * OUT_ROW + 1024] = v;
    }
    #undef WROW
    #undef WBUF
    #undef WMB
}

// ================= fallback kernel (proven R9 cp.async path) =================
#define FB_STAGES 3
#define FB_GRID   608
#define CH_FLTS (CH_ROWS * F_GEN)

__device__ __forceinline__ void issue_warp(float* wbuf, const float* gwarp, int lane) {
    const int j = lane & 15;
    #pragma unroll
    for (int k = 0; k < 8; k++) {
        int row = 2 * k + (lane >> 4);
        int slot = j ^ (row & 7);
        cp16(&wbuf[row * 64 + slot * 4], gwarp + row * 64 + j * 4);
    }
}

__global__ void __launch_bounds__(THREADS, 4)
fused_model_kernel(const float* __restrict__ x_gen,
                   const float* __restrict__ W_gen,
                   const float* __restrict__ b_gen,
                   const float* __restrict__ W_val,
                   const float* __restrict__ b_val,
                   const float* __restrict__ param,
                   const float* __restrict__ high,
                   float* __restrict__ out)
{
    __shared__ __align__(1024) float sX[FB_STAGES][CH_FLTS];
    __shared__ float sred[40];

    const int bid  = blockIdx.x;
    const int t    = threadIdx.x;
    const int warp = t >> 5;
    const int lane = t & 31;

    const int nb    = (B_DIM - 1 - bid) / FB_GRID + 1;
    const int total = nb * CH_PER_B;

    #define WPTR(i) (x_gen + (size_t)(bid + ((i) >> 3) * FB_GRID) * (N_GENN * F_GEN) \
                           + ((i) & 7) * CH_FLTS + warp * WR_FLTS)

    issue_warp(&sX[0][warp * WR_FLTS], WPTR(0), lane);   CP_COMMIT();
    issue_warp(&sX[1][warp * WR_FLTS], WPTR(1), lane);   CP_COMMIT();

    const float s0 = 1.0f / (1.0f + expf(-param[0]));
    const float s1 = 0.5f / (1.0f + expf(-param[1]));

    unsigned braw[2][8][2], blo[2][8][2];
    {
        const int kk = lane & 3, nn = lane >> 2;
        #pragma unroll
        for (int nt = 0; nt < 2; nt++)
            #pragma unroll
            for (int ks = 0; ks < 8; ks++)
                #pragma unroll
                for (int h = 0; h < 2; h++) {
                    float w = __ldg(&W_gen[(kk + 4 * h + 8 * ks) * EMB + nn + 8 * nt]);
                    unsigned whi = __float_as_uint(w) & 0xFFFFE000u;
                    braw[nt][ks][h] = __float_as_uint(w);
                    blo[nt][ks][h]  = __float_as_uint(w - __uint_as_float(whi));
                }
    }
    float bias[2][2];
    #pragma unroll
    for (int nt = 0; nt < 2; nt++) {
        bias[nt][0] = __ldg(&b_gen[2 * (lane & 3) + 8 * nt]);
        bias[nt][1] = __ldg(&b_gen[2 * (lane & 3) + 8 * nt + 1]);
    }

    const int hiu  = lane >> 4;
    const int rxor = (lane & 15) & 7;
    const unsigned lane_off = (lane & 15) * 256;

    float vpart = 0.0f;

    #pragma unroll 1
    for (int i = 0; i < total; i++) {
        const int ch = i & 7;
        if (i + 2 < total) {
            issue_warp(&sX[(i + 2) % FB_STAGES][warp * WR_FLTS], WPTR(i + 2), lane);
            CP_COMMIT();
            CP_WAIT(2);
        } else {
            if (i == total - 2) CP_WAIT(1);
            else                CP_WAIT(0);
        }
        __syncwarp();

        if (ch == 0) {
            float* orow = out + (size_t)(bid + (i >> 3) * FB_GRID) * OUT_ROW;
            #pragma unroll
            for (int j = 0; j < 8; j++) {
                int idx = t + THREADS * j;
                float h = __ldg(&high[idx >> 1]);
                orow[idx] = (idx & 1) ? s1 * h : s0 * h;
            }
        }

        float c[2][2][4];
        #pragma unroll
        for (int nt = 0; nt < 2; nt++) {
            c[nt][0][0] = c[nt][0][2] = bias[nt][0];
            c[nt][0][1] = c[nt][0][3] = bias[nt][1];
            c[nt][1][0] = c[nt][1][1] = c[nt][1][2] = c[nt][1][3] = 0.0f;
        }

        const unsigned sbase = s2u(&sX[i % FB_STAGES][warp * WR_FLTS]) + lane_off;

        #pragma unroll
        for (int ks = 0; ks < 8; ks++) {
            unsigned raw[4];
            ldsm4(raw, sbase + (((2 * ks + hiu) ^ rxor) << 4));
            unsigned alo[4];
            #pragma unroll
            for (int j = 0; j < 4; j++) {
                float x  = __uint_as_float(raw[j]);
                float hi = __uint_as_float(__float_as_uint(x) & 0xFFFFE000u);
                alo[j] = __float_as_uint(x - hi);
            }
            const int p = ks & 1;
            #pragma unroll
            for (int nt = 0; nt < 2; nt++) {
                mma_tf32(c[nt][p], alo, braw[nt][ks][0], braw[nt][ks][1]);
                mma_tf32(c[nt][p], raw, blo[nt][ks][0],  blo[nt][ks][1]);
                mma_tf32(c[nt][p], raw, braw[nt][ks][0], braw[nt][ks][1]);
            }
        }

        const int r1 = ch * CH_ROWS + warp * 16 + (lane >> 2);
        const int r2 = r1 + 8;
        #pragma unroll
        for (int nt = 0; nt < 2; nt++) {
            const int n0 = 2 * (lane & 3) + 8 * nt;
            float2 w1 = __ldg(reinterpret_cast<const float2*>(W_val + r1 * EMB + n0));
            float2 w2 = __ldg(reinterpret_cast<const float2*>(W_val + r2 * EMB + n0));
            vpart += fmaxf(c[nt][0][0] + c[nt][1][0], 0.0f) * w1.x
                   + fmaxf(c[nt][0][1] + c[nt][1][1], 0.0f) * w1.y
                   + fmaxf(c[nt][0][2] + c[nt][1][2], 0.0f) * w2.x
                   + fmaxf(c[nt][0][3] + c[nt][1][3], 0.0f) * w2.y;
        }

        if (ch == 7) {
            #pragma unroll
            for (int o = 16; o > 0; o >>= 1)
                vpart += __shfl_down_sync(0xffffffff, vpart, o);
            if (lane == 0) sred[(i >> 3) * 4 + warp] = vpart;
            vpart = 0.0f;
        }
    }

    __syncthreads();
    if (t < nb) {
        float v = ((sred[t * 4 + 0] + sred[t * 4 + 1])
                 + (sred[t * 4 + 2] + sred[t * 4 + 3])) + b_val[0];
        out[(size_t)(bid + t * FB_GRID) * OUT_ROW + 1024] = v;
    }
    #undef WPTR
}

// ================= host =================

typedef CUresult (*PFN_encodeTiled)(
    CUtensorMap*, CUtensorMapDataType, cuuint32_t, void*,
    const cuuint64_t*, const cuuint64_t*, const cuuint32_t*, const cuuint32_t*,
    CUtensorMapInterleave, CUtensorMapSwizzle, CUtensorMapL2promotion,
    CUtensorMapFloatOOBfill);

extern "C" void kernel_launch(void* const* d_in, const int* in_sizes, int n_in,
                              void* d_out, int out_size)
{
    const float* x_gen = (const float*)d_in[0];
    const float* W_gen = (const float*)d_in[1];
    const float* b_gen = (const float*)d_in[2];
    const float* W_val = (const float*)d_in[3];
    const float* b_val = (const float*)d_in[4];
    const float* param = (const float*)d_in[5];
    const float* high  = (const float*)d_in[6];
    float* out = (float*)d_out;

    static PFN_encodeTiled enc = nullptr;
    static bool probed = false;
    if (!probed) {
        probed = true;
        void* p = nullptr;
        cudaDriverEntryPointQueryResult qr;
        if (cudaGetDriverEntryPoint("cuTensorMapEncodeTiled", &p,
                                    cudaEnableDefault, &qr) == cudaSuccess &&
            qr == cudaDriverEntryPointSuccess)
            enc = (PFN_encodeTiled)p;
        if (enc)
            cudaFuncSetAttribute(fused_tma_kernel,
                                 cudaFuncAttributeMaxDynamicSharedMemorySize,
                                 SMEM_BYTES);
    }

    if (enc) {
        CUtensorMap tmap;
        cuuint64_t gdim[2]    = {F_GEN, (cuuint64_t)B_DIM * N_GENN};
        cuuint64_t gstride[1] = {F_GEN * sizeof(float)};
        cuuint32_t box[2]     = {32, 16};
        cuuint32_t estr[2]    = {1, 1};
        CUresult r = enc(&tmap, CU_TENSOR_MAP_DATA_TYPE_FLOAT32, 2, (void*)x_gen,
                         gdim, gstride, box, estr,
                         CU_TENSOR_MAP_INTERLEAVE_NONE, CU_TENSOR_MAP_SWIZZLE_128B,
                         CU_TENSOR_MAP_L2_PROMOTION_L2_128B,
                         CU_TENSOR_MAP_FLOAT_OOB_FILL_NONE);
        if (r == CUDA_SUCCESS) {
            fused_tma_kernel<<<GRID, THREADS, SMEM_BYTES>>>(
                tmap, W_gen, b_gen, W_val, b_val, param, high, out);
            return;
        }
    }
    fused_model_kernel<<<FB_GRID, THREADS>>>(
        x_gen, W_gen, b_gen, W_val, b_val, param, high, out);
}